// round 3
// baseline (speedup 1.0000x reference)
#include <cuda_runtime.h>

#define NNODES 100000
#define NEDGES 3200000
#define DIN 64
#define HID 16
#define SCAN_BLK 1024
#define SCAN_CHUNK 4096
#define NSCANBLK 25   // ceil(NNODES / SCAN_CHUNK)

// ---------------- device scratch (no allocations allowed) -------------------
__device__ __align__(256) float g_p1[NNODES * HID];     // x@W1x + b_msg1
__device__ __align__(256) float g_s1[NNODES * HID];     // x@W_skip1 + b_skip1
__device__ __align__(256) float g_p2[NNODES * HID];     // h@W2x + b_msg2
__device__ __align__(256) float g_s2[NNODES * HID];     // h@W_skip2 + b_skip2
__device__ __align__(256) float g_acce[NNODES * HID];   // per-node sum of edge_attr
__device__ __align__(256) unsigned g_deg[NNODES];
__device__ __align__(256) unsigned g_off[NNODES + 1];
__device__ __align__(256) unsigned g_cur[NNODES];
__device__ __align__(256) uint2    g_edg[NEDGES];       // (src, eid) sorted by dst
__device__ unsigned g_bsum[NSCANBLK];
__device__ unsigned g_boff[NSCANBLK];

// ---------------------------------------------------------------------------
// K0: zero degree counters (400 KB)
// ---------------------------------------------------------------------------
__global__ __launch_bounds__(256) void k_zero() {
    int i = blockIdx.x * blockDim.x + threadIdx.x;
    if (i < NNODES) g_deg[i] = 0u;
}

// ---------------------------------------------------------------------------
// K1: histogram of dst (integer REDs, 4 edges/thread)
// ---------------------------------------------------------------------------
__global__ __launch_bounds__(256) void k_hist(const int* __restrict__ dst) {
    int i = blockIdx.x * blockDim.x + threadIdx.x;
    if (i < NEDGES / 4) {
        int4 d = __ldg(reinterpret_cast<const int4*>(dst) + i);
        atomicAdd(&g_deg[d.x], 1u);
        atomicAdd(&g_deg[d.y], 1u);
        atomicAdd(&g_deg[d.z], 1u);
        atomicAdd(&g_deg[d.w], 1u);
    }
}

// ---------------------------------------------------------------------------
// K2a/b/c: exclusive prefix scan of g_deg -> g_off (two-level)
// ---------------------------------------------------------------------------
__global__ __launch_bounds__(SCAN_BLK) void k_scan1() {
    __shared__ unsigned swarp[32];
    int t = threadIdx.x;
    int base = blockIdx.x * SCAN_CHUNK + t * 4;
    unsigned v[4];
    #pragma unroll
    for (int i = 0; i < 4; i++) v[i] = (base + i < NNODES) ? g_deg[base + i] : 0u;
    unsigned s = v[0] + v[1] + v[2] + v[3];
    unsigned lane = t & 31, wid = t >> 5;
    unsigned inc = s;
    #pragma unroll
    for (int o = 1; o < 32; o <<= 1) {
        unsigned n = __shfl_up_sync(~0u, inc, o);
        if (lane >= o) inc += n;
    }
    if (lane == 31) swarp[wid] = inc;
    __syncthreads();
    if (wid == 0) {
        unsigned wv = swarp[lane];
        #pragma unroll
        for (int o = 1; o < 32; o <<= 1) {
            unsigned n = __shfl_up_sync(~0u, wv, o);
            if (lane >= o) wv += n;
        }
        swarp[lane] = wv;
    }
    __syncthreads();
    unsigned run = inc - s + (wid ? swarp[wid - 1] : 0u);
    #pragma unroll
    for (int i = 0; i < 4; i++) {
        if (base + i < NNODES) g_off[base + i] = run;
        run += v[i];
    }
    if (t == 0) g_bsum[blockIdx.x] = swarp[31];
}

__global__ void k_scan2() {
    int lane = threadIdx.x;
    unsigned v = (lane < NSCANBLK) ? g_bsum[lane] : 0u;
    unsigned inc = v;
    #pragma unroll
    for (int o = 1; o < 32; o <<= 1) {
        unsigned n = __shfl_up_sync(~0u, inc, o);
        if (lane >= o) inc += n;
    }
    if (lane < NSCANBLK) g_boff[lane] = inc - v;
}

__global__ __launch_bounds__(256) void k_scan3() {
    int i = blockIdx.x * blockDim.x + threadIdx.x;
    if (i < NNODES) {
        unsigned val = g_off[i] + g_boff[i >> 12];   // /SCAN_CHUNK
        g_off[i] = val;
        g_cur[i] = val;
    }
    if (i == 0) g_off[NNODES] = NEDGES;
}

// ---------------------------------------------------------------------------
// K3: scatter (src, eid) into dst-sorted CSR slots
// ---------------------------------------------------------------------------
__global__ __launch_bounds__(256) void k_scatter(const int* __restrict__ src,
                                                 const int* __restrict__ dst) {
    int e = blockIdx.x * blockDim.x + threadIdx.x;
    if (e < NEDGES) {
        int d = __ldg(dst + e);
        unsigned pos = atomicAdd(&g_cur[d], 1u);
        g_edg[pos] = make_uint2((unsigned)__ldg(src + e), (unsigned)e);
    }
}

// ---------------------------------------------------------------------------
// K4: per-node p1 = x@W1x + b_msg1 ; s1 = x@W_skip1 + b_skip1
// ---------------------------------------------------------------------------
__global__ __launch_bounds__(256) void k_node1(
    const float* __restrict__ x,
    const float* __restrict__ Wm1, const float* __restrict__ bm1,
    const float* __restrict__ Ws1, const float* __restrict__ bs1)
{
    __shared__ float sWx[DIN * HID];
    __shared__ float sWs[DIN * HID];
    __shared__ float sx[16][DIN];
    int t = threadIdx.x;
    for (int i = t; i < DIN * HID; i += 256) { sWx[i] = Wm1[i]; sWs[i] = Ws1[i]; }
    int ln = t >> 4, j = t & 15;
    int v = blockIdx.x * 16 + ln;
    if (v < NNODES) {
        reinterpret_cast<float4*>(sx[ln])[j] =
            reinterpret_cast<const float4*>(x + (size_t)v * DIN)[j];
    }
    __syncthreads();
    if (v >= NNODES) return;
    float ap = bm1[j], as = bs1[j];
    #pragma unroll
    for (int k = 0; k < DIN; k++) {
        float xv = sx[ln][k];
        ap = fmaf(xv, sWx[k * HID + j], ap);
        as = fmaf(xv, sWs[k * HID + j], as);
    }
    g_p1[(size_t)v * HID + j] = ap;
    g_s1[(size_t)v * HID + j] = as;
}

// ---------------------------------------------------------------------------
// K5: gather-aggregate conv1 + fused node math (warp per node, 8 nodes/block)
//   accp = sum p1[src] ; acce = sum edge_attr[eid]
//   h  = relu(accp + acce@We1 + s1)
//   p2 = h@W2x + b_msg2 ; s2 = h@W_skip2 + b_skip2 ; store acce
// ---------------------------------------------------------------------------
__global__ __launch_bounds__(256) void k_agg1(
    const float* __restrict__ ea,
    const float* __restrict__ Wm1,
    const float* __restrict__ Wm2, const float* __restrict__ bm2,
    const float* __restrict__ Ws2, const float* __restrict__ bs2)
{
    __shared__ float sWe1[HID * HID], sW2x[HID * HID], sWs2[HID * HID];
    __shared__ float sb2[HID], sbs2[HID];
    __shared__ float sacc[8][32];
    __shared__ float sh[8][HID];
    int t = threadIdx.x;
    if (t < 256) { sWe1[t] = Wm1[DIN * HID + t]; sW2x[t] = Wm2[t]; sWs2[t] = Ws2[t]; }
    if (t < HID) { sb2[t] = bm2[t]; sbs2[t] = bs2[t]; }

    int w = t >> 5, lane = t & 31;
    int v = blockIdx.x * 8 + w;            // grid chosen so v < NNODES always
    int slot = lane >> 2, c = lane & 3;
    unsigned beg = g_off[v], end = g_off[v + 1];
    float4 ap = make_float4(0.f, 0.f, 0.f, 0.f);
    float4 ae = make_float4(0.f, 0.f, 0.f, 0.f);
    for (unsigned idx = beg + slot; idx < end; idx += 8) {
        uint2 se = g_edg[idx];
        float4 p = __ldg(reinterpret_cast<const float4*>(g_p1 + (size_t)se.x * HID) + c);
        float4 e = __ldg(reinterpret_cast<const float4*>(ea + (size_t)se.y * HID) + c);
        ap.x += p.x; ap.y += p.y; ap.z += p.z; ap.w += p.w;
        ae.x += e.x; ae.y += e.y; ae.z += e.z; ae.w += e.w;
    }
    #pragma unroll
    for (int m = 4; m <= 16; m <<= 1) {
        ap.x += __shfl_xor_sync(~0u, ap.x, m);
        ap.y += __shfl_xor_sync(~0u, ap.y, m);
        ap.z += __shfl_xor_sync(~0u, ap.z, m);
        ap.w += __shfl_xor_sync(~0u, ap.w, m);
        ae.x += __shfl_xor_sync(~0u, ae.x, m);
        ae.y += __shfl_xor_sync(~0u, ae.y, m);
        ae.z += __shfl_xor_sync(~0u, ae.z, m);
        ae.w += __shfl_xor_sync(~0u, ae.w, m);
    }
    if (lane < 4) {
        reinterpret_cast<float4*>(sacc[w])[c] = ap;
        reinterpret_cast<float4*>(sacc[w] + 16)[c] = ae;
    }
    __syncthreads();

    int ln = t >> 4, j = t & 15;
    if (t < 128) {
        int v2 = blockIdx.x * 8 + ln;
        float hv = sacc[ln][j] + g_s1[(size_t)v2 * HID + j];
        #pragma unroll
        for (int k = 0; k < HID; k++) hv = fmaf(sacc[ln][16 + k], sWe1[k * HID + j], hv);
        sh[ln][j] = fmaxf(hv, 0.f);
        g_acce[(size_t)v2 * HID + j] = sacc[ln][16 + j];
    }
    __syncthreads();
    if (t < 128) {
        int v2 = blockIdx.x * 8 + ln;
        float pv = sb2[j], sv = sbs2[j];
        #pragma unroll
        for (int k = 0; k < HID; k++) {
            float hk = sh[ln][k];
            pv = fmaf(hk, sW2x[k * HID + j], pv);
            sv = fmaf(hk, sWs2[k * HID + j], sv);
        }
        g_p2[(size_t)v2 * HID + j] = pv;
        g_s2[(size_t)v2 * HID + j] = sv;
    }
}

// ---------------------------------------------------------------------------
// K6: gather-aggregate conv2 + fused final projection
//   accp2 = sum p2[src] ; h2 = accp2 + acce@We2 + s2 ; out = h2@W_lin3 + b
// ---------------------------------------------------------------------------
__global__ __launch_bounds__(256) void k_agg2(
    const float* __restrict__ Wm2,
    const float* __restrict__ Wl3, const float* __restrict__ bl3,
    float* __restrict__ out)
{
    __shared__ float sWe2[HID * HID];
    __shared__ float sWl[HID * DIN];
    __shared__ float sbl[DIN];
    __shared__ float sacc[8][HID];
    __shared__ float sae[8][HID];
    __shared__ float sh2[8][HID];
    int t = threadIdx.x;
    if (t < 256) sWe2[t] = Wm2[HID * HID + t];
    for (int i = t; i < HID * DIN; i += 256) sWl[i] = Wl3[i];
    if (t < DIN) sbl[t] = bl3[t];

    int w = t >> 5, lane = t & 31;
    int v = blockIdx.x * 8 + w;
    int slot = lane >> 2, c = lane & 3;
    unsigned beg = g_off[v], end = g_off[v + 1];
    float4 ap = make_float4(0.f, 0.f, 0.f, 0.f);
    for (unsigned idx = beg + slot; idx < end; idx += 8) {
        uint2 se = g_edg[idx];
        float4 p = __ldg(reinterpret_cast<const float4*>(g_p2 + (size_t)se.x * HID) + c);
        ap.x += p.x; ap.y += p.y; ap.z += p.z; ap.w += p.w;
    }
    #pragma unroll
    for (int m = 4; m <= 16; m <<= 1) {
        ap.x += __shfl_xor_sync(~0u, ap.x, m);
        ap.y += __shfl_xor_sync(~0u, ap.y, m);
        ap.z += __shfl_xor_sync(~0u, ap.z, m);
        ap.w += __shfl_xor_sync(~0u, ap.w, m);
    }
    if (lane < 4) reinterpret_cast<float4*>(sacc[w])[c] = ap;

    int ln = t >> 4, j = t & 15;
    __syncthreads();
    if (t < 128) {
        int v2 = blockIdx.x * 8 + ln;
        sae[ln][j] = g_acce[(size_t)v2 * HID + j];
    }
    __syncthreads();
    if (t < 128) {
        int v2 = blockIdx.x * 8 + ln;
        float hv = sacc[ln][j] + g_s2[(size_t)v2 * HID + j];
        #pragma unroll
        for (int k = 0; k < HID; k++) hv = fmaf(sae[ln][k], sWe2[k * HID + j], hv);
        sh2[ln][j] = hv;
    }
    __syncthreads();

    // 8 nodes x 64 outputs = 512 per block, 2 per thread
    #pragma unroll
    for (int r = 0; r < 2; r++) {
        int o = t + r * 256;
        int ln2 = o >> 6, col = o & 63;
        int v3 = blockIdx.x * 8 + ln2;
        float acc = sbl[col];
        #pragma unroll
        for (int k = 0; k < HID; k++) acc = fmaf(sh2[ln2][k], sWl[k * DIN + col], acc);
        out[(size_t)v3 * DIN + col] = acc;
    }
}

// ---------------------------------------------------------------------------
extern "C" void kernel_launch(void* const* d_in, const int* in_sizes, int n_in,
                              void* d_out, int out_size)
{
    const float* x   = (const float*)d_in[0];
    const int*   ei  = (const int*)  d_in[1];
    const float* ea  = (const float*)d_in[2];
    const float* Wm1 = (const float*)d_in[3];
    const float* bm1 = (const float*)d_in[4];
    const float* Ws1 = (const float*)d_in[5];
    const float* bs1 = (const float*)d_in[6];
    const float* Wm2 = (const float*)d_in[7];
    const float* bm2 = (const float*)d_in[8];
    const float* Ws2 = (const float*)d_in[9];
    const float* bs2 = (const float*)d_in[10];
    const float* Wl3 = (const float*)d_in[11];
    const float* bl3 = (const float*)d_in[12];
    const int* src = ei;
    const int* dst = ei + NEDGES;
    float* out = (float*)d_out;

    k_zero   <<<(NNODES + 255) / 256, 256>>>();
    k_hist   <<<(NEDGES / 4 + 255) / 256, 256>>>(dst);
    k_node1  <<<(NNODES + 15) / 16, 256>>>(x, Wm1, bm1, Ws1, bs1);
    k_scan1  <<<NSCANBLK, SCAN_BLK>>>();
    k_scan2  <<<1, 32>>>();
    k_scan3  <<<(NNODES + 255) / 256, 256>>>();
    k_scatter<<<(NEDGES + 255) / 256, 256>>>(src, dst);
    k_agg1   <<<NNODES / 8, 256>>>(ea, Wm1, Wm2, bm2, Ws2, bs2);
    k_agg2   <<<NNODES / 8, 256>>>(Wm2, Wl3, bl3, out);
}

// round 4
// speedup vs baseline: 1.0495x; 1.0495x over previous
#include <cuda_runtime.h>

#define NNODES 100000
#define NEDGES 3200000
#define DIN 64
#define HID 16
#define SCAN_BLK 1024
#define SCAN_CHUNK 4096
#define NSCANBLK 25   // ceil(NNODES / SCAN_CHUNK)

// ---------------- device scratch (no allocations allowed) -------------------
__device__ __align__(256) float g_p1[NNODES * HID];     // x@W1x + b_msg1
__device__ __align__(256) float g_s1[NNODES * HID];     // x@W_skip1 + b_skip1
__device__ __align__(256) float g_p2[NNODES * HID];     // h@W2x + b_msg2
__device__ __align__(256) float g_s2[NNODES * HID];     // h@W_skip2 + b_skip2
__device__ __align__(256) float g_acce[NNODES * HID];   // per-node sum of edge_attr (scatter)
__device__ __align__(256) unsigned g_deg[NNODES];
__device__ __align__(256) unsigned g_off[NNODES + 1];
__device__ __align__(256) unsigned g_cur[NNODES];
__device__ __align__(256) unsigned g_srcs[NEDGES];      // src ids sorted by dst (CSR)
__device__ unsigned g_bsum[NSCANBLK];
__device__ unsigned g_boff[NSCANBLK];

__device__ __forceinline__ void red_v4(float* addr, float4 v) {
    asm volatile("red.global.add.v4.f32 [%0], {%1,%2,%3,%4};"
                 :: "l"(addr), "f"(v.x), "f"(v.y), "f"(v.z), "f"(v.w)
                 : "memory");
}

// ---------------------------------------------------------------------------
// K0: zero acc_e (6.4 MB) + degree counters
// ---------------------------------------------------------------------------
__global__ __launch_bounds__(256) void k_zero() {
    int i = blockIdx.x * blockDim.x + threadIdx.x;
    const int nacc = NNODES * 4;                       // g_acce as float4
    if (i < nacc) reinterpret_cast<float4*>(g_acce)[i] = make_float4(0.f, 0.f, 0.f, 0.f);
    else if (i < nacc + NNODES) g_deg[i - nacc] = 0u;
}

// ---------------------------------------------------------------------------
// K1: histogram of dst
// ---------------------------------------------------------------------------
__global__ __launch_bounds__(256) void k_hist(const int* __restrict__ dst) {
    int i = blockIdx.x * blockDim.x + threadIdx.x;
    if (i < NEDGES / 4) {
        int4 d = __ldg(reinterpret_cast<const int4*>(dst) + i);
        atomicAdd(&g_deg[d.x], 1u);
        atomicAdd(&g_deg[d.y], 1u);
        atomicAdd(&g_deg[d.z], 1u);
        atomicAdd(&g_deg[d.w], 1u);
    }
}

// ---------------------------------------------------------------------------
// K2a/b/c: exclusive prefix scan of g_deg -> g_off (two-level)
// ---------------------------------------------------------------------------
__global__ __launch_bounds__(SCAN_BLK) void k_scan1() {
    __shared__ unsigned swarp[32];
    int t = threadIdx.x;
    int base = blockIdx.x * SCAN_CHUNK + t * 4;
    unsigned v[4];
    #pragma unroll
    for (int i = 0; i < 4; i++) v[i] = (base + i < NNODES) ? g_deg[base + i] : 0u;
    unsigned s = v[0] + v[1] + v[2] + v[3];
    unsigned lane = t & 31, wid = t >> 5;
    unsigned inc = s;
    #pragma unroll
    for (int o = 1; o < 32; o <<= 1) {
        unsigned n = __shfl_up_sync(~0u, inc, o);
        if (lane >= o) inc += n;
    }
    if (lane == 31) swarp[wid] = inc;
    __syncthreads();
    if (wid == 0) {
        unsigned wv = swarp[lane];
        #pragma unroll
        for (int o = 1; o < 32; o <<= 1) {
            unsigned n = __shfl_up_sync(~0u, wv, o);
            if (lane >= o) wv += n;
        }
        swarp[lane] = wv;
    }
    __syncthreads();
    unsigned run = inc - s + (wid ? swarp[wid - 1] : 0u);
    #pragma unroll
    for (int i = 0; i < 4; i++) {
        if (base + i < NNODES) g_off[base + i] = run;
        run += v[i];
    }
    if (t == 0) g_bsum[blockIdx.x] = swarp[31];
}

__global__ void k_scan2() {
    int lane = threadIdx.x;
    unsigned v = (lane < NSCANBLK) ? g_bsum[lane] : 0u;
    unsigned inc = v;
    #pragma unroll
    for (int o = 1; o < 32; o <<= 1) {
        unsigned n = __shfl_up_sync(~0u, inc, o);
        if (lane >= o) inc += n;
    }
    if (lane < NSCANBLK) g_boff[lane] = inc - v;
}

__global__ __launch_bounds__(256) void k_scan3() {
    int i = blockIdx.x * blockDim.x + threadIdx.x;
    if (i < NNODES) {
        unsigned val = g_off[i] + g_boff[i >> 12];   // /SCAN_CHUNK
        g_off[i] = val;
        g_cur[i] = val;
    }
    if (i == 0) g_off[NNODES] = NEDGES;
}

// ---------------------------------------------------------------------------
// K3: scatter src into dst-sorted CSR slots (4B payload)
// ---------------------------------------------------------------------------
__global__ __launch_bounds__(256) void k_scatter(const int* __restrict__ src,
                                                 const int* __restrict__ dst) {
    int e = blockIdx.x * blockDim.x + threadIdx.x;
    if (e < NEDGES) {
        int d = __ldg(dst + e);
        unsigned pos = atomicAdd(&g_cur[d], 1u);
        g_srcs[pos] = (unsigned)__ldg(src + e);
    }
}

// ---------------------------------------------------------------------------
// K4: streaming ea scatter — acc_e[dst] += edge_attr[e]  (4 lanes/edge, coalesced)
// ---------------------------------------------------------------------------
__global__ __launch_bounds__(256) void k_edge_ea(const int* __restrict__ dst,
                                                 const float* __restrict__ ea) {
    int tid = blockIdx.x * blockDim.x + threadIdx.x;
    if (tid >= NEDGES * 4) return;
    int i = tid >> 2, c = tid & 3;
    float4 e = reinterpret_cast<const float4*>(ea)[tid];   // coalesced stream
    int d = __ldg(dst + i);
    red_v4(g_acce + (size_t)d * HID + c * 4, e);
}

// ---------------------------------------------------------------------------
// K5: per-node p1 = x@W1x + b_msg1 ; s1 = x@W_skip1 + b_skip1
// ---------------------------------------------------------------------------
__global__ __launch_bounds__(256) void k_node1(
    const float* __restrict__ x,
    const float* __restrict__ Wm1, const float* __restrict__ bm1,
    const float* __restrict__ Ws1, const float* __restrict__ bs1)
{
    __shared__ float sWx[DIN * HID];
    __shared__ float sWs[DIN * HID];
    __shared__ float sx[16][DIN];
    int t = threadIdx.x;
    for (int i = t; i < DIN * HID; i += 256) { sWx[i] = Wm1[i]; sWs[i] = Ws1[i]; }
    int ln = t >> 4, j = t & 15;
    int v = blockIdx.x * 16 + ln;
    if (v < NNODES) {
        reinterpret_cast<float4*>(sx[ln])[j] =
            reinterpret_cast<const float4*>(x + (size_t)v * DIN)[j];
    }
    __syncthreads();
    if (v >= NNODES) return;
    float ap = bm1[j], as = bs1[j];
    #pragma unroll
    for (int k = 0; k < DIN; k++) {
        float xv = sx[ln][k];
        ap = fmaf(xv, sWx[k * HID + j], ap);
        as = fmaf(xv, sWs[k * HID + j], as);
    }
    g_p1[(size_t)v * HID + j] = ap;
    g_s1[(size_t)v * HID + j] = as;
}

// ---------------------------------------------------------------------------
// K6: conv1 gather-aggregate (p1 only, L2-resident) + fused node math
//   accp = sum p1[src] ; h = relu(accp + acce@We1 + s1)
//   p2 = h@W2x + b_msg2 ; s2 = h@W_skip2 + b_skip2
// ---------------------------------------------------------------------------
__global__ __launch_bounds__(256) void k_agg1(
    const float* __restrict__ Wm1,
    const float* __restrict__ Wm2, const float* __restrict__ bm2,
    const float* __restrict__ Ws2, const float* __restrict__ bs2)
{
    __shared__ float sWe1[HID * HID], sW2x[HID * HID], sWs2[HID * HID];
    __shared__ float sb2[HID], sbs2[HID];
    __shared__ float sacc[8][HID];
    __shared__ float sae[8][HID];
    __shared__ float sh[8][HID];
    int t = threadIdx.x;
    if (t < 256) { sWe1[t] = Wm1[DIN * HID + t]; sW2x[t] = Wm2[t]; sWs2[t] = Ws2[t]; }
    if (t < HID) { sb2[t] = bm2[t]; sbs2[t] = bs2[t]; }

    int w = t >> 5, lane = t & 31;
    int v = blockIdx.x * 8 + w;            // grid = NNODES/8 exactly
    int slot = lane >> 2, c = lane & 3;
    unsigned beg = g_off[v], end = g_off[v + 1];
    if (lane < HID) sae[w][lane] = g_acce[(size_t)v * HID + lane];
    float4 ap = make_float4(0.f, 0.f, 0.f, 0.f);
    for (unsigned idx = beg + slot; idx < end; idx += 8) {
        unsigned s = __ldg(g_srcs + idx);
        float4 p = __ldg(reinterpret_cast<const float4*>(g_p1 + (size_t)s * HID) + c);
        ap.x += p.x; ap.y += p.y; ap.z += p.z; ap.w += p.w;
    }
    #pragma unroll
    for (int m = 4; m <= 16; m <<= 1) {
        ap.x += __shfl_xor_sync(~0u, ap.x, m);
        ap.y += __shfl_xor_sync(~0u, ap.y, m);
        ap.z += __shfl_xor_sync(~0u, ap.z, m);
        ap.w += __shfl_xor_sync(~0u, ap.w, m);
    }
    if (lane < 4) reinterpret_cast<float4*>(sacc[w])[lane] = ap;
    __syncthreads();

    int ln = t >> 4, j = t & 15;
    if (t < 128) {
        int v2 = blockIdx.x * 8 + ln;
        float hv = sacc[ln][j] + g_s1[(size_t)v2 * HID + j];
        #pragma unroll
        for (int k = 0; k < HID; k++) hv = fmaf(sae[ln][k], sWe1[k * HID + j], hv);
        sh[ln][j] = fmaxf(hv, 0.f);
    }
    __syncthreads();
    if (t < 128) {
        int v2 = blockIdx.x * 8 + ln;
        float pv = sb2[j], sv = sbs2[j];
        #pragma unroll
        for (int k = 0; k < HID; k++) {
            float hk = sh[ln][k];
            pv = fmaf(hk, sW2x[k * HID + j], pv);
            sv = fmaf(hk, sWs2[k * HID + j], sv);
        }
        g_p2[(size_t)v2 * HID + j] = pv;
        g_s2[(size_t)v2 * HID + j] = sv;
    }
}

// ---------------------------------------------------------------------------
// K7: conv2 gather-aggregate + fused final projection
//   accp2 = sum p2[src] ; h2 = accp2 + acce@We2 + s2 ; out = h2@W_lin3 + b
// ---------------------------------------------------------------------------
__global__ __launch_bounds__(256) void k_agg2(
    const float* __restrict__ Wm2,
    const float* __restrict__ Wl3, const float* __restrict__ bl3,
    float* __restrict__ out)
{
    __shared__ float sWe2[HID * HID];
    __shared__ float sWl[HID * DIN];
    __shared__ float sbl[DIN];
    __shared__ float sacc[8][HID];
    __shared__ float sae[8][HID];
    __shared__ float sh2[8][HID];
    int t = threadIdx.x;
    if (t < 256) sWe2[t] = Wm2[HID * HID + t];
    for (int i = t; i < HID * DIN; i += 256) sWl[i] = Wl3[i];
    if (t < DIN) sbl[t] = bl3[t];

    int w = t >> 5, lane = t & 31;
    int v = blockIdx.x * 8 + w;
    int slot = lane >> 2, c = lane & 3;
    unsigned beg = g_off[v], end = g_off[v + 1];
    if (lane < HID) sae[w][lane] = g_acce[(size_t)v * HID + lane];
    float4 ap = make_float4(0.f, 0.f, 0.f, 0.f);
    for (unsigned idx = beg + slot; idx < end; idx += 8) {
        unsigned s = __ldg(g_srcs + idx);
        float4 p = __ldg(reinterpret_cast<const float4*>(g_p2 + (size_t)s * HID) + c);
        ap.x += p.x; ap.y += p.y; ap.z += p.z; ap.w += p.w;
    }
    #pragma unroll
    for (int m = 4; m <= 16; m <<= 1) {
        ap.x += __shfl_xor_sync(~0u, ap.x, m);
        ap.y += __shfl_xor_sync(~0u, ap.y, m);
        ap.z += __shfl_xor_sync(~0u, ap.z, m);
        ap.w += __shfl_xor_sync(~0u, ap.w, m);
    }
    if (lane < 4) reinterpret_cast<float4*>(sacc[w])[lane] = ap;
    __syncthreads();

    int ln = t >> 4, j = t & 15;
    if (t < 128) {
        int v2 = blockIdx.x * 8 + ln;
        float hv = sacc[ln][j] + g_s2[(size_t)v2 * HID + j];
        #pragma unroll
        for (int k = 0; k < HID; k++) hv = fmaf(sae[ln][k], sWe2[k * HID + j], hv);
        sh2[ln][j] = hv;
    }
    __syncthreads();

    // 8 nodes x 64 outputs = 512 per block, 2 per thread
    #pragma unroll
    for (int r = 0; r < 2; r++) {
        int o = t + r * 256;
        int ln2 = o >> 6, col = o & 63;
        int v3 = blockIdx.x * 8 + ln2;
        float acc = sbl[col];
        #pragma unroll
        for (int k = 0; k < HID; k++) acc = fmaf(sh2[ln2][k], sWl[k * DIN + col], acc);
        out[(size_t)v3 * DIN + col] = acc;
    }
}

// ---------------------------------------------------------------------------
extern "C" void kernel_launch(void* const* d_in, const int* in_sizes, int n_in,
                              void* d_out, int out_size)
{
    const float* x   = (const float*)d_in[0];
    const int*   ei  = (const int*)  d_in[1];
    const float* ea  = (const float*)d_in[2];
    const float* Wm1 = (const float*)d_in[3];
    const float* bm1 = (const float*)d_in[4];
    const float* Ws1 = (const float*)d_in[5];
    const float* bs1 = (const float*)d_in[6];
    const float* Wm2 = (const float*)d_in[7];
    const float* bm2 = (const float*)d_in[8];
    const float* Ws2 = (const float*)d_in[9];
    const float* bs2 = (const float*)d_in[10];
    const float* Wl3 = (const float*)d_in[11];
    const float* bl3 = (const float*)d_in[12];
    const int* src = ei;
    const int* dst = ei + NEDGES;
    float* out = (float*)d_out;

    // Order chosen so the profiled launch (4th) is k_edge_ea.
    k_zero   <<<(NNODES * 5 + 255) / 256, 256>>>();
    k_hist   <<<(NEDGES / 4 + 255) / 256, 256>>>(dst);
    k_scan1  <<<NSCANBLK, SCAN_BLK>>>();
    k_edge_ea<<<(NEDGES * 4 + 255) / 256, 256>>>(dst, ea);
    k_scan2  <<<1, 32>>>();
    k_scan3  <<<(NNODES + 255) / 256, 256>>>();
    k_scatter<<<(NEDGES + 255) / 256, 256>>>(src, dst);
    k_node1  <<<(NNODES + 15) / 16, 256>>>(x, Wm1, bm1, Ws1, bs1);
    k_agg1   <<<NNODES / 8, 256>>>(Wm1, Wm2, bm2, Ws2, bs2);
    k_agg2   <<<NNODES / 8, 256>>>(Wm2, Wl3, bl3, out);
}